// round 15
// baseline (speedup 1.0000x reference)
#include <cuda_runtime.h>
#include <cstdint>
#include <cstddef>

// Problem constants
#define T_  4
#define B_  1024
#define S_  64          // WH*WW
#define C_  256
#define NPAIR 4         // head pairs (64 j each)
#define NGR 35          // 4*35 = 140 CTAs -> 8 SMs reserved for concurrent zfill
#define QKTHREADS 1024
#define IDXSTRIDE 272   // uint32 slots per (token,t); 1088B, 16B aligned
#define Y_ELEMS (67108864LL)   // T*B*S*C

// packed fp32x2 helpers (sm_103a)
#define ADD_F32X2(out, a, b) \
    asm("add.rn.f32x2 %0, %1, %2;" : "=l"(out) : "l"(a), "l"(b))
#define PACK_F32X2(out, lo, hi) \
    asm("mov.b64 %0, {%1, %2};" : "=l"(out) : "r"(lo), "r"(hi))
#define UNPACK_F32X2(lo, hi, in) \
    asm("mov.b64 {%0, %1}, %2;" : "=r"(lo), "=r"(hi) : "l"(in))

// ---------------- device scratch (statics only) ----------------
__device__ float4   g_Wpack4[NPAIR * 256 * 32];          // per-pair QK weights, 512 KB
__device__ float    g_WpT[C_ * C_];                      // Wp transposed, 256 KB
__device__ uint32_t g_off[(size_t)B_ * S_ * T_ * IDXSTRIDE]; // prescaled offsets
__device__ unsigned long long g_cnt[(size_t)B_ * S_];    // 4 x 16-bit exact counts / token
__device__ uint32_t g_kbits[(size_t)T_ * B_ * S_ * 8];   // k spike bits, 8 MB
__device__ uint8_t  g_att[(size_t)T_ * B_ * 8 * S_];     // att spikes, 2 MB

// ---------------- streams/events: created before harness checkpoints ----------------
namespace {
struct StreamPack {
    cudaStream_t s2;
    cudaEvent_t eL, eZ;
    StreamPack() {
        cudaStreamCreateWithFlags(&s2, cudaStreamNonBlocking);
        cudaEventCreateWithFlags(&eL, cudaEventDisableTiming);
        cudaEventCreateWithFlags(&eZ, cudaEventDisableTiming);
    }
};
StreamPack g_sp;
}

// ---------------- prep: pack Wq/Wk per-pair lane-major float4 ----------------
__global__ void prep_pack(const float* __restrict__ Wq, const float* __restrict__ Wk) {
    int idx = blockIdx.x * 256 + threadIdx.x;   // 0..32767
    int lane = idx & 31, c = (idx >> 5) & 255, p = idx >> 13;
    int j0 = p * 64 + lane, j1 = j0 + 32;
    g_Wpack4[idx] = make_float4(__ldg(Wq + j0 * C_ + c), __ldg(Wk + j0 * C_ + c),
                                __ldg(Wq + j1 * C_ + c), __ldg(Wk + j1 * C_ + c));
}

__global__ void prep_wp(const float* __restrict__ Wp) {
    __shared__ float t[32][33];
    int tx = threadIdx.x, ty = threadIdx.y;
    int j0 = blockIdx.y * 32, c0 = blockIdx.x * 32;
    t[ty][tx] = Wp[(j0 + ty) * C_ + c0 + tx];
    __syncthreads();
    g_WpT[(c0 + ty) * C_ + j0 + tx] = t[tx][ty];
}

// ---------------- K1: LIF -> compacted lists; warp-scan prefix (frozen) ----------------
__global__ void __launch_bounds__(512) lif_mask(const float* __restrict__ x) {
    const int sp2 = blockIdx.x;          // token pair 0..31
    const int b   = blockIdx.y;
    const int tid = threadIdx.x;
    const int half = tid >> 8;           // token within pair
    const int c = tid & 255;             // channel
    const int warp8 = c >> 5;            // channel-group warp 0..7
    const int lane = c & 31;
    const int s = sp2 * 2 + half;
    const int tok = b * 64 + s;

    __shared__ uint32_t smask[2][T_][8];
    __shared__ uint32_t sbase[2][T_][8];
    __shared__ uint32_t stot[2][T_];

    bool spv[T_];
    uint32_t mym[T_];

    {
        float v = 0.0f;
        const float* xp = x + (size_t)b * 16384 + (size_t)s * 256 + c;
#pragma unroll
        for (int t = 0; t < T_; t++) {
            float xv = __ldg(xp + (size_t)t * 16777216);
            v += (xv - v) * 0.5f;
            bool sp = (v - 1.0f) >= 0.0f;
            spv[t] = sp;
            if (sp) v = 0.0f;
            uint32_t m = __ballot_sync(0xffffffffu, sp);
            mym[t] = m;
            if (lane == 0) smask[half][t][warp8] = m;
        }
    }
    __syncthreads();

    if ((tid & 255) < 32) {
        const int t = lane >> 3, w = lane & 7;
        uint32_t cw = __popc(smask[half][t][w]);
        uint32_t scan = cw;
#pragma unroll
        for (int d = 1; d < 8; d <<= 1) {
            uint32_t u = __shfl_up_sync(0xffffffffu, scan, d);
            if ((lane & 7) >= d) scan += u;
        }
        sbase[half][t][w] = scan - cw;
        if (w == 7) stot[half][t] = scan;
    }
    __syncthreads();

    uint32_t* ib = g_off + (size_t)tok * (T_ * IDXSTRIDE);
    const uint32_t lmask = (1u << lane) - 1u;
#pragma unroll
    for (int t = 0; t < T_; t++) {
        if (spv[t]) {
            int pos = sbase[half][t][warp8] + __popc(mym[t] & lmask);
            ib[t * IDXSTRIDE + pos] = (uint32_t)(c << 9);
        }
    }
    if (c == 0) {
        unsigned long long pack = 0;
#pragma unroll
        for (int t = 0; t < T_; t++)
            pack |= (unsigned long long)stot[half][t] << (t * 16);
        g_cnt[tok] = pack;
    }
}

// ---------------- K2: sparse Q/K matvec, 2 heads per CTA, exact-count tail ----------------
extern __shared__ char sWraw[];   // qk: 256*512 B = 131072

#define QK_VISIT(OFS)                                                   \
    {                                                                   \
        const ulonglong2 wv = *(const ulonglong2*)(laneBase + (OFS));   \
        ADD_F32X2(acc0, acc0, wv.x);                                    \
        ADD_F32X2(acc1, acc1, wv.y);                                    \
    }

__global__ void __launch_bounds__(QKTHREADS) qk_kernel(const float* __restrict__ pos) {
    const int p   = blockIdx.x;          // head pair: heads 2p, 2p+1
    const int grp = blockIdx.y;
    const int tid = threadIdx.x, warp = tid >> 5, lane = tid & 31;

    {
        const uint4* src = (const uint4*)(g_Wpack4 + p * 8192);
        uint4* dst = (uint4*)sWraw;
        for (int i = tid; i < 8192; i += QKTHREADS) dst[i] = src[i];
    }
    __syncthreads();

    const int tok0 = (grp * 65536) / NGR;
    const int tok1 = ((grp + 1) * 65536) / NGR;
    const int j0 = p * 64 + lane, j1 = j0 + 32;
    const int h0 = 2 * p;
    const char* laneBase = sWraw + lane * 16;

    for (int i = tok0 + warp; i < tok1; i += (QKTHREADS / 32)) {
        const int b = i >> 6, s = i & 63;
        const unsigned long long cpack = __ldg(g_cnt + i);
        const uint32_t* ib = g_off + (size_t)i * (T_ * IDXSTRIDE);

        float vq0 = 0.f, vk0 = 0.f, va0 = 0.f;
        float vq1 = 0.f, vk1 = 0.f, va1 = 0.f;
#pragma unroll
        for (int t = 0; t < T_; t++) {
            const int cnt = (int)((cpack >> (t * 16)) & 0xFFFF);

            unsigned long long acc0, acc1;
            {
                float p0 = __ldg(pos + (t * 64 + s) * 256 + j0);
                float p1 = __ldg(pos + (t * 64 + s) * 256 + j1);
                PACK_F32X2(acc0, __float_as_uint(0.0f), __float_as_uint(p0));
                PACK_F32X2(acc1, __float_as_uint(0.0f), __float_as_uint(p1));
            }

            const uint4* gp = (const uint4*)(ib + t * IDXSTRIDE);
            const int g4 = cnt >> 2;
            for (int g = 0; g < g4; g++) {
                uint4 w = __ldg(gp + g);
                QK_VISIT(w.x)
                QK_VISIT(w.y)
                QK_VISIT(w.z)
                QK_VISIT(w.w)
            }
            const int rem = cnt & 3;       // warp-uniform tail, no sentinel traffic
            if (rem) {
                uint4 w = __ldg(gp + g4);
                QK_VISIT(w.x)
                if (rem > 1) QK_VISIT(w.y)
                if (rem > 2) QK_VISIT(w.z)
            }

            uint32_t aqb0, akb0, aqb1, akb1;
            UNPACK_F32X2(aqb0, akb0, acc0);
            UNPACK_F32X2(aqb1, akb1, acc1);
            float aq0 = __uint_as_float(aqb0), ak0 = __uint_as_float(akb0);
            float aq1 = __uint_as_float(aqb1), ak1 = __uint_as_float(akb1);

            // LIF (exact same arithmetic/order as reference)
            vq0 += (aq0 - vq0) * 0.5f; bool sq0 = (vq0 - 1.f) >= 0.f; if (sq0) vq0 = 0.f;
            vk0 += (ak0 - vk0) * 0.5f; bool sk0 = (vk0 - 1.f) >= 0.f; if (sk0) vk0 = 0.f;
            vq1 += (aq1 - vq1) * 0.5f; bool sq1 = (vq1 - 1.f) >= 0.f; if (sq1) vq1 = 0.f;
            vk1 += (ak1 - vk1) * 0.5f; bool sk1 = (vk1 - 1.f) >= 0.f; if (sk1) vk1 = 0.f;

            uint32_t kb0 = __ballot_sync(0xffffffffu, sk0);
            uint32_t kb1 = __ballot_sync(0xffffffffu, sk1);
            int cq0 = __popc(__ballot_sync(0xffffffffu, sq0));
            int cq1 = __popc(__ballot_sync(0xffffffffu, sq1));
            va0 += ((float)cq0 - va0) * 0.5f; bool sa0 = (va0 - 1.f) >= 0.f; if (sa0) va0 = 0.f;
            va1 += ((float)cq1 - va1) * 0.5f; bool sa1 = (va1 - 1.f) >= 0.f; if (sa1) va1 = 0.f;

            if (lane == 0) {
                size_t kbase = (((size_t)t * B_ + b) * S_ + s) * 8;
                g_kbits[kbase + h0]     = kb0;
                g_kbits[kbase + h0 + 1] = kb1;
                size_t abase = ((size_t)t * B_ + b) * 8;
                g_att[(abase + h0) * 64 + s]     = sa0 ? 1u : 0u;
                g_att[(abase + h0 + 1) * 64 + s] = sa1 ? 1u : 0u;
            }
        }
    }
}

// ---------------- K3: per-(j-slice, 2 b) CTA; Wp staged once; y half only (frozen) ----------------
__global__ void __launch_bounds__(512) kernelB(const float* __restrict__ bp,
                                               float* __restrict__ out) {
    extern __shared__ char sB[];
    float4*   sWp  = (float4*)sB;                    // [c*8 + jq]
    uint32_t* skb  = (uint32_t*)(sB + 32768);        // [h][t][wh][ww]
    uint8_t*  satt = (uint8_t*)(sB + 32768 + 8192);  // [h][t][s]

    const int q8 = blockIdx.x;       // 32-j slice
    const int tid = threadIdx.x;

    {
        const float4* src = (const float4*)g_WpT;
        for (int idx = tid; idx < 2048; idx += 512) {
            int c = idx >> 3, l = idx & 7;
            sWp[idx] = __ldg(src + c * 64 + q8 * 8 + l);
        }
    }

    const int jq = tid & 7;
    const int s  = tid >> 3;
    const int wh = s >> 3, ww = s & 7;

    unsigned long long b01, b23;
    {
        const float4 bj = __ldg((const float4*)bp + q8 * 8 + jq);
        PACK_F32X2(b01, __float_as_uint(bj.x), __float_as_uint(bj.y));
        PACK_F32X2(b23, __float_as_uint(bj.z), __float_as_uint(bj.w));
    }

#pragma unroll
    for (int bb = 0; bb < 2; bb++) {
        const int b = blockIdx.y * 2 + bb;
        const int t_k = b >> 8;

        if (bb) __syncthreads();   // all readers of previous masks done

        for (int idx = tid; idx < 2048; idx += 512) {
            int h = idx >> 8, t = (idx >> 6) & 3, wh2 = (idx >> 3) & 7, ww2 = idx & 7;
            int b_k = (b & 255) * 4 + (h >> 1);
            int s_k = ((h & 1) << 5) + t * 8 + wh2;
            skb[idx] = __ldg(&g_kbits[(((size_t)t_k * B_ + b_k) * S_ + s_k) * 8 + ww2]);
        }
        for (int idx = tid; idx < 2048; idx += 512) {
            int h = idx >> 8, t = (idx >> 6) & 3, s2 = idx & 63;
            int b_k = (b & 255) * 4 + (h >> 1);
            int h_a = (h & 1) * 4 + t;
            satt[idx] = __ldg(&g_att[(((size_t)t_k * B_ + b_k) * 8 + h_a) * S_ + s2]);
        }
        __syncthreads();

#pragma unroll
        for (int t = 0; t < T_; t++) {
            unsigned long long acc01 = b01, acc23 = b23;
#pragma unroll
            for (int w = 0; w < 8; w++) {
                uint32_t m = satt[w * 256 + t * 64 + s] ? skb[w * 256 + t * 64 + wh * 8 + ww] : 0u;
                while (m) {
                    int c = (w << 5) + __ffs(m) - 1;
                    m &= m - 1;
                    const ulonglong2 wv = *(const ulonglong2*)(sWp + c * 8 + jq);
                    ADD_F32X2(acc01, acc01, wv.x);
                    ADD_F32X2(acc23, acc23, wv.y);
                }
            }
            uint32_t a0, a1, a2, a3;
            UNPACK_F32X2(a0, a1, acc01);
            UNPACK_F32X2(a2, a3, acc23);
            float4 res = make_float4(__uint_as_float(a0), __uint_as_float(a1),
                                     __uint_as_float(a2), __uint_as_float(a3));

            size_t off = (((size_t)t * B_ + b) * S_ + s) * 256 + q8 * 32 + jq * 4;
            *(float4*)(out + off) = res;
        }
    }
}

// ---------------- zero-fill attn_out half (+tail): short CTAs, overlaps qk on spare SMs ----------------
// attn_out = lif(x2) is identically zero: x2 in {0,1}, v <- (v+x)/2 < 1 always (exact).
__global__ void zfill4(float4* __restrict__ p, size_t n4) {
    size_t base = ((size_t)blockIdx.x * blockDim.x + threadIdx.x) * 16;
    float4 z = make_float4(0.f, 0.f, 0.f, 0.f);
#pragma unroll
    for (int k = 0; k < 16; k++) {
        size_t i = base + k;
        if (i < n4) p[i] = z;
    }
}
__global__ void zfill_tail(float* __restrict__ p, size_t n) {
    size_t i = (size_t)blockIdx.x * blockDim.x + threadIdx.x;
    if (i < n) p[i] = 0.f;
}

extern "C" void kernel_launch(void* const* d_in, const int* in_sizes, int n_in,
                              void* d_out, int out_size) {
    const float* x   = (const float*)d_in[0];
    const float* Wq  = (const float*)d_in[1];
    const float* Wk  = (const float*)d_in[2];
    const float* Wp  = (const float*)d_in[3];
    const float* bp  = (const float*)d_in[4];
    const float* pos = (const float*)d_in[5];
    float* out = (float*)d_out;

    cudaFuncSetAttribute(qk_kernel, cudaFuncAttributeMaxDynamicSharedMemorySize, 131072);
    cudaFuncSetAttribute(kernelB, cudaFuncAttributeMaxDynamicSharedMemorySize, 43008);

    // main chain: preps -> lif -> qk(140 CTAs) -> kernelB
    prep_pack<<<128, 256>>>(Wq, Wk);
    prep_wp<<<dim3(8, 8), dim3(32, 32)>>>(Wp);
    lif_mask<<<dim3(32, 1024), 512>>>(x);

    // fork zero-fill after lif: short CTAs run on the 8 SMs qk leaves free.
    bool have_zero = ((long long)out_size > Y_ELEMS);
    if (have_zero) {
        cudaEventRecord(g_sp.eL, 0);
        cudaStreamWaitEvent(g_sp.s2, g_sp.eL, 0);
        size_t extra = (size_t)((long long)out_size - Y_ELEMS);
        size_t n4 = extra / 4;
        if (n4 > 0) {
            int blocks = (int)((n4 + 256 * 16 - 1) / (256 * 16));
            zfill4<<<blocks, 256, 0, g_sp.s2>>>((float4*)(out + Y_ELEMS), n4);
        }
        size_t tail = extra - n4 * 4;
        if (tail > 0)
            zfill_tail<<<1, 256, 0, g_sp.s2>>>(out + Y_ELEMS + n4 * 4, tail);
        cudaEventRecord(g_sp.eZ, g_sp.s2);
    }

    qk_kernel<<<dim3(NPAIR, NGR), QKTHREADS, 131072>>>(pos);
    kernelB<<<dim3(8, 512), 512, 43008>>>(bp, out);

    if (have_zero) cudaStreamWaitEvent(0, g_sp.eZ, 0);
}

// round 16
// speedup vs baseline: 1.2728x; 1.2728x over previous
#include <cuda_runtime.h>
#include <cstdint>
#include <cstddef>

// Problem constants
#define T_  4
#define B_  1024
#define S_  64          // WH*WW
#define C_  256
#define NPAIR 4         // head pairs (64 j each)
#define NGR 37          // 4*37 = 148 CTAs = one wave @ 1 CTA/SM (qk)
#define QKTHREADS 1024
#define IDXSTRIDE 272   // uint32 slots per (token,t); 1088B, 16B aligned
#define Y_ELEMS (67108864LL)   // T*B*S*C

// packed fp32x2 helpers (sm_103a)
#define ADD_F32X2(out, a, b) \
    asm("add.rn.f32x2 %0, %1, %2;" : "=l"(out) : "l"(a), "l"(b))
#define PACK_F32X2(out, lo, hi) \
    asm("mov.b64 %0, {%1, %2};" : "=l"(out) : "r"(lo), "r"(hi))
#define UNPACK_F32X2(lo, hi, in) \
    asm("mov.b64 {%0, %1}, %2;" : "=r"(lo), "=r"(hi) : "l"(in))

// ---------------- device scratch (statics only) ----------------
__device__ float4   g_Wpack4[NPAIR * 256 * 32];          // per-pair QK weights, 512 KB
__device__ float    g_WpT[C_ * C_];                      // Wp transposed, 256 KB
__device__ uint32_t g_off[(size_t)B_ * S_ * T_ * IDXSTRIDE]; // prescaled offsets
__device__ unsigned long long g_cnt[(size_t)B_ * S_];    // 4 x 16-bit exact counts / token
__device__ uint32_t g_kbits[(size_t)T_ * B_ * S_ * 8];   // k spike bits, 8 MB
__device__ uint8_t  g_att[(size_t)T_ * B_ * 8 * S_];     // att spikes, 2 MB

// ---------------- prep: pack Wq/Wk per-pair lane-major float4 ----------------
__global__ void prep_pack(const float* __restrict__ Wq, const float* __restrict__ Wk) {
    int idx = blockIdx.x * 256 + threadIdx.x;   // 0..32767
    int lane = idx & 31, c = (idx >> 5) & 255, p = idx >> 13;
    int j0 = p * 64 + lane, j1 = j0 + 32;
    g_Wpack4[idx] = make_float4(__ldg(Wq + j0 * C_ + c), __ldg(Wk + j0 * C_ + c),
                                __ldg(Wq + j1 * C_ + c), __ldg(Wk + j1 * C_ + c));
}

__global__ void prep_wp(const float* __restrict__ Wp) {
    __shared__ float t[32][33];
    int tx = threadIdx.x, ty = threadIdx.y;
    int j0 = blockIdx.y * 32, c0 = blockIdx.x * 32;
    t[ty][tx] = Wp[(j0 + ty) * C_ + c0 + tx];
    __syncthreads();
    g_WpT[(c0 + ty) * C_ + j0 + tx] = t[tx][ty];
}

// ---------------- K1: LIF -> compacted lists + fused attn_out zero-fill ----------------
// Grid (32, 1024), 512 threads = 2 tokens x 256 channels.
// attn_out = lif(x2) is identically zero: x2 in {0,1}, v <- (v+x)/2 < 1 always
// (exact dyadic fp32; reference computes the same arithmetic). Each CTA zeroes
// the 8 KB of attn_out belonging to its (b, 2 tokens) with one coalesced
// STG.128 per thread, issued before the LIF loads so it hides under LDG latency.
__global__ void __launch_bounds__(512) lif_mask(const float* __restrict__ x,
                                                float* __restrict__ outz, int write_zero) {
    const int sp2 = blockIdx.x;          // token pair 0..31
    const int b   = blockIdx.y;
    const int tid = threadIdx.x;
    const int half = tid >> 8;           // token within pair
    const int c = tid & 255;             // channel
    const int warp8 = c >> 5;            // channel-group warp 0..7
    const int lane = c & 31;
    const int s = sp2 * 2 + half;
    const int tok = b * 64 + s;

    // Fused zero-fill of attn_out for this CTA's 8 (t, token) rows.
    if (write_zero) {
        const int chunk = tid >> 6;              // 0..7 -> (t, token-half)
        const int tz = chunk >> 1, sz = sp2 * 2 + (chunk & 1);
        size_t off = ((((size_t)tz * B_ + b) * S_ + sz) * 256) + (size_t)(tid & 63) * 4;
        *(float4*)(outz + off) = make_float4(0.f, 0.f, 0.f, 0.f);
    }

    __shared__ uint32_t smask[2][T_][8];
    __shared__ uint32_t sbase[2][T_][8];
    __shared__ uint32_t stot[2][T_];

    bool spv[T_];
    uint32_t mym[T_];

    {
        float v = 0.0f;
        const float* xp = x + (size_t)b * 16384 + (size_t)s * 256 + c;
#pragma unroll
        for (int t = 0; t < T_; t++) {
            float xv = __ldg(xp + (size_t)t * 16777216);
            v += (xv - v) * 0.5f;
            bool sp = (v - 1.0f) >= 0.0f;
            spv[t] = sp;
            if (sp) v = 0.0f;
            uint32_t m = __ballot_sync(0xffffffffu, sp);
            mym[t] = m;
            if (lane == 0) smask[half][t][warp8] = m;
        }
    }
    __syncthreads();

    if ((tid & 255) < 32) {
        const int t = lane >> 3, w = lane & 7;
        uint32_t cw = __popc(smask[half][t][w]);
        uint32_t scan = cw;
#pragma unroll
        for (int d = 1; d < 8; d <<= 1) {
            uint32_t u = __shfl_up_sync(0xffffffffu, scan, d);
            if ((lane & 7) >= d) scan += u;
        }
        sbase[half][t][w] = scan - cw;
        if (w == 7) stot[half][t] = scan;
    }
    __syncthreads();

    uint32_t* ib = g_off + (size_t)tok * (T_ * IDXSTRIDE);
    const uint32_t lmask = (1u << lane) - 1u;
#pragma unroll
    for (int t = 0; t < T_; t++) {
        if (spv[t]) {
            int pos = sbase[half][t][warp8] + __popc(mym[t] & lmask);
            ib[t * IDXSTRIDE + pos] = (uint32_t)(c << 9);
        }
    }
    if (c == 0) {
        unsigned long long pack = 0;
#pragma unroll
        for (int t = 0; t < T_; t++)
            pack |= (unsigned long long)stot[half][t] << (t * 16);
        g_cnt[tok] = pack;
    }
}

// ---------------- K2: sparse Q/K matvec, 2 heads per CTA, exact-count tail (frozen) ----------------
extern __shared__ char sWraw[];   // qk: 256*512 B = 131072

#define QK_VISIT(OFS)                                                   \
    {                                                                   \
        const ulonglong2 wv = *(const ulonglong2*)(laneBase + (OFS));   \
        ADD_F32X2(acc0, acc0, wv.x);                                    \
        ADD_F32X2(acc1, acc1, wv.y);                                    \
    }

__global__ void __launch_bounds__(QKTHREADS) qk_kernel(const float* __restrict__ pos) {
    const int p   = blockIdx.x;          // head pair: heads 2p, 2p+1
    const int grp = blockIdx.y;
    const int tid = threadIdx.x, warp = tid >> 5, lane = tid & 31;

    {
        const uint4* src = (const uint4*)(g_Wpack4 + p * 8192);
        uint4* dst = (uint4*)sWraw;
        for (int i = tid; i < 8192; i += QKTHREADS) dst[i] = src[i];
    }
    __syncthreads();

    const int tok0 = (grp * 65536) / NGR;
    const int tok1 = ((grp + 1) * 65536) / NGR;
    const int j0 = p * 64 + lane, j1 = j0 + 32;
    const int h0 = 2 * p;
    const char* laneBase = sWraw + lane * 16;

    for (int i = tok0 + warp; i < tok1; i += (QKTHREADS / 32)) {
        const int b = i >> 6, s = i & 63;
        const unsigned long long cpack = __ldg(g_cnt + i);
        const uint32_t* ib = g_off + (size_t)i * (T_ * IDXSTRIDE);

        float vq0 = 0.f, vk0 = 0.f, va0 = 0.f;
        float vq1 = 0.f, vk1 = 0.f, va1 = 0.f;
#pragma unroll
        for (int t = 0; t < T_; t++) {
            const int cnt = (int)((cpack >> (t * 16)) & 0xFFFF);

            unsigned long long acc0, acc1;
            {
                float p0 = __ldg(pos + (t * 64 + s) * 256 + j0);
                float p1 = __ldg(pos + (t * 64 + s) * 256 + j1);
                PACK_F32X2(acc0, __float_as_uint(0.0f), __float_as_uint(p0));
                PACK_F32X2(acc1, __float_as_uint(0.0f), __float_as_uint(p1));
            }

            const uint4* gp = (const uint4*)(ib + t * IDXSTRIDE);
            const int g4 = cnt >> 2;
            for (int g = 0; g < g4; g++) {
                uint4 w = __ldg(gp + g);
                QK_VISIT(w.x)
                QK_VISIT(w.y)
                QK_VISIT(w.z)
                QK_VISIT(w.w)
            }
            const int rem = cnt & 3;       // warp-uniform tail, no sentinel traffic
            if (rem) {
                uint4 w = __ldg(gp + g4);
                QK_VISIT(w.x)
                if (rem > 1) QK_VISIT(w.y)
                if (rem > 2) QK_VISIT(w.z)
            }

            uint32_t aqb0, akb0, aqb1, akb1;
            UNPACK_F32X2(aqb0, akb0, acc0);
            UNPACK_F32X2(aqb1, akb1, acc1);
            float aq0 = __uint_as_float(aqb0), ak0 = __uint_as_float(akb0);
            float aq1 = __uint_as_float(aqb1), ak1 = __uint_as_float(akb1);

            // LIF (exact same arithmetic/order as reference)
            vq0 += (aq0 - vq0) * 0.5f; bool sq0 = (vq0 - 1.f) >= 0.f; if (sq0) vq0 = 0.f;
            vk0 += (ak0 - vk0) * 0.5f; bool sk0 = (vk0 - 1.f) >= 0.f; if (sk0) vk0 = 0.f;
            vq1 += (aq1 - vq1) * 0.5f; bool sq1 = (vq1 - 1.f) >= 0.f; if (sq1) vq1 = 0.f;
            vk1 += (ak1 - vk1) * 0.5f; bool sk1 = (vk1 - 1.f) >= 0.f; if (sk1) vk1 = 0.f;

            uint32_t kb0 = __ballot_sync(0xffffffffu, sk0);
            uint32_t kb1 = __ballot_sync(0xffffffffu, sk1);
            int cq0 = __popc(__ballot_sync(0xffffffffu, sq0));
            int cq1 = __popc(__ballot_sync(0xffffffffu, sq1));
            va0 += ((float)cq0 - va0) * 0.5f; bool sa0 = (va0 - 1.f) >= 0.f; if (sa0) va0 = 0.f;
            va1 += ((float)cq1 - va1) * 0.5f; bool sa1 = (va1 - 1.f) >= 0.f; if (sa1) va1 = 0.f;

            if (lane == 0) {
                size_t kbase = (((size_t)t * B_ + b) * S_ + s) * 8;
                g_kbits[kbase + h0]     = kb0;
                g_kbits[kbase + h0 + 1] = kb1;
                size_t abase = ((size_t)t * B_ + b) * 8;
                g_att[(abase + h0) * 64 + s]     = sa0 ? 1u : 0u;
                g_att[(abase + h0 + 1) * 64 + s] = sa1 ? 1u : 0u;
            }
        }
    }
}

// ---------------- K3: per-(j-slice, 2 b) CTA; Wp staged once; y half only (frozen) ----------------
__global__ void __launch_bounds__(512) kernelB(const float* __restrict__ bp,
                                               float* __restrict__ out) {
    extern __shared__ char sB[];
    float4*   sWp  = (float4*)sB;                    // [c*8 + jq]
    uint32_t* skb  = (uint32_t*)(sB + 32768);        // [h][t][wh][ww]
    uint8_t*  satt = (uint8_t*)(sB + 32768 + 8192);  // [h][t][s]

    const int q8 = blockIdx.x;       // 32-j slice
    const int tid = threadIdx.x;

    {
        const float4* src = (const float4*)g_WpT;
        for (int idx = tid; idx < 2048; idx += 512) {
            int c = idx >> 3, l = idx & 7;
            sWp[idx] = __ldg(src + c * 64 + q8 * 8 + l);
        }
    }

    const int jq = tid & 7;
    const int s  = tid >> 3;
    const int wh = s >> 3, ww = s & 7;

    unsigned long long b01, b23;
    {
        const float4 bj = __ldg((const float4*)bp + q8 * 8 + jq);
        PACK_F32X2(b01, __float_as_uint(bj.x), __float_as_uint(bj.y));
        PACK_F32X2(b23, __float_as_uint(bj.z), __float_as_uint(bj.w));
    }

#pragma unroll
    for (int bb = 0; bb < 2; bb++) {
        const int b = blockIdx.y * 2 + bb;
        const int t_k = b >> 8;

        if (bb) __syncthreads();   // all readers of previous masks done

        for (int idx = tid; idx < 2048; idx += 512) {
            int h = idx >> 8, t = (idx >> 6) & 3, wh2 = (idx >> 3) & 7, ww2 = idx & 7;
            int b_k = (b & 255) * 4 + (h >> 1);
            int s_k = ((h & 1) << 5) + t * 8 + wh2;
            skb[idx] = __ldg(&g_kbits[(((size_t)t_k * B_ + b_k) * S_ + s_k) * 8 + ww2]);
        }
        for (int idx = tid; idx < 2048; idx += 512) {
            int h = idx >> 8, t = (idx >> 6) & 3, s2 = idx & 63;
            int b_k = (b & 255) * 4 + (h >> 1);
            int h_a = (h & 1) * 4 + t;
            satt[idx] = __ldg(&g_att[(((size_t)t_k * B_ + b_k) * 8 + h_a) * S_ + s2]);
        }
        __syncthreads();

#pragma unroll
        for (int t = 0; t < T_; t++) {
            unsigned long long acc01 = b01, acc23 = b23;
#pragma unroll
            for (int w = 0; w < 8; w++) {
                uint32_t m = satt[w * 256 + t * 64 + s] ? skb[w * 256 + t * 64 + wh * 8 + ww] : 0u;
                while (m) {
                    int c = (w << 5) + __ffs(m) - 1;
                    m &= m - 1;
                    const ulonglong2 wv = *(const ulonglong2*)(sWp + c * 8 + jq);
                    ADD_F32X2(acc01, acc01, wv.x);
                    ADD_F32X2(acc23, acc23, wv.y);
                }
            }
            uint32_t a0, a1, a2, a3;
            UNPACK_F32X2(a0, a1, acc01);
            UNPACK_F32X2(a2, a3, acc23);
            float4 res = make_float4(__uint_as_float(a0), __uint_as_float(a1),
                                     __uint_as_float(a2), __uint_as_float(a3));

            size_t off = (((size_t)t * B_ + b) * S_ + s) * 256 + q8 * 32 + jq * 4;
            *(float4*)(out + off) = res;
        }
    }
}

__global__ void zfill_tail(float* __restrict__ p, size_t n) {
    size_t i = (size_t)blockIdx.x * blockDim.x + threadIdx.x;
    if (i < n) p[i] = 0.f;
}

extern "C" void kernel_launch(void* const* d_in, const int* in_sizes, int n_in,
                              void* d_out, int out_size) {
    const float* x   = (const float*)d_in[0];
    const float* Wq  = (const float*)d_in[1];
    const float* Wk  = (const float*)d_in[2];
    const float* Wp  = (const float*)d_in[3];
    const float* bp  = (const float*)d_in[4];
    const float* pos = (const float*)d_in[5];
    float* out = (float*)d_out;

    cudaFuncSetAttribute(qk_kernel, cudaFuncAttributeMaxDynamicSharedMemorySize, 131072);
    cudaFuncSetAttribute(kernelB, cudaFuncAttributeMaxDynamicSharedMemorySize, 43008);

    int write_zero = ((long long)out_size >= 2 * Y_ELEMS) ? 1 : 0;

    // strictly serial single-stream chain (overlap attempts R12/R14/R15 all lost)
    prep_pack<<<128, 256>>>(Wq, Wk);
    prep_wp<<<dim3(8, 8), dim3(32, 32)>>>(Wp);
    lif_mask<<<dim3(32, 1024), 512>>>(x, out + Y_ELEMS, write_zero);
    qk_kernel<<<dim3(NPAIR, NGR), QKTHREADS, 131072>>>(pos);
    kernelB<<<dim3(8, 512), 512, 43008>>>(bp, out);

    long long extra = (long long)out_size - (write_zero ? 2 * Y_ELEMS : Y_ELEMS);
    if (extra > 0) {
        long long base = write_zero ? 2 * Y_ELEMS : Y_ELEMS;
        int blocks = (int)((extra + 255) / 256);
        zfill_tail<<<blocks, 256>>>(out + base, (size_t)extra);
    }
}